// round 1
// baseline (speedup 1.0000x reference)
#include <cuda_runtime.h>
#include <cstdint>

#define B_SZ  8
#define SEQ   4096
#define HID   1024
#define NWRD  (HID / 32)     // 32 ballot words per (b, t)
#define DMAX  64             // FIR truncation: g[d] ~ 0.16^d, underflows long before 64
#define TC    512            // t-chunk per y-kernel block

// ---------------- scratch (device globals; no allocation allowed) ----------------
__device__ unsigned g_spikebits[B_SZ][NWRD][SEQ];   // 4 MB: bit h%32 of word [b][h/32][t]
__device__ float    g_g[DMAX];                       // impulse response C A^d B
__device__ float    g_y[B_SZ][SEQ];                  // y[b][t]

// ---------------- pass 1: LIF neurons -> spike bitmasks --------------------------
// 128 blocks x 64 threads: one warp per SMSP on 128 SMs; each thread owns one
// (b, h) lane and runs the 4096-step recursion with distance-2 register prefetch.
__global__ void __launch_bounds__(64, 1) snn_kernel(const float* __restrict__ x)
{
    const int blk  = blockIdx.x;        // 0..127
    const int b    = blk >> 4;          // 16 blocks per batch
    const int hblk = blk & 15;
    const int tid  = threadIdx.x;       // 0..63
    const int lane = tid & 31;
    const int h    = hblk * 64 + tid;   // global hidden index
    const int wh   = h >> 5;            // word index 0..31

    const float* xp = x + (size_t)b * SEQ * HID + h;
    unsigned* sb = &g_spikebits[b][wh][0];

    float xbuf[2][32];
    #pragma unroll
    for (int i = 0; i < 32; i++) xbuf[0][i] = xp[(size_t)i * HID];
    #pragma unroll
    for (int i = 0; i < 32; i++) xbuf[1][i] = xp[(size_t)(32 + i) * HID];

    float v = 0.0f, r = 0.0f;

    #pragma unroll 2
    for (int c = 0; c < SEQ / 32; c++) {
        const int  cur = c & 1;
        const bool pf  = (c < SEQ / 32 - 2);
        const int  tpf = (c + 2) * 32;
        unsigned mymask = 0;

        #pragma unroll
        for (int i = 0; i < 32; i++) {
            float xi = xbuf[cur][i];
            if (pf) xbuf[cur][i] = xp[(size_t)(tpf + i) * HID];  // prefetch c+2

            // v = v*0.9 + x  (unfused: match XLA mul+add exactly at the threshold)
            float vn = __fadd_rn(__fmul_rn(v, 0.9f), xi);
            bool spike = (vn >= 1.0f) && (r <= 0.0f);
            v = spike ? 0.0f : vn;
            float rd = fmaxf(__fadd_rn(r, -1.0f), 0.0f);
            r = spike ? 5.0f : rd;

            unsigned m = __ballot_sync(0xffffffffu, spike);
            if (lane == i) mymask = m;           // lane i keeps step i's mask
        }
        sb[c * 32 + lane] = mymask;              // coalesced 128B store per warp
    }
}

// ---------------- pass 2a: impulse response g[d] = C * A^d * B -------------------
__global__ void g_kernel(const float* __restrict__ A,
                         const float* __restrict__ Bv,
                         const float* __restrict__ Cv)
{
    __shared__ float As[64 * 65];   // padded: bank-conflict-free row access
    __shared__ float Wd[64 * 65];   // Wd[d*65+j] = (A^d B)[j]
    __shared__ float ws[64];
    __shared__ float cs[64];

    const int tid = threadIdx.x;    // 64 threads
    for (int i = tid; i < 64 * 64; i += 64) {
        int n = i >> 6, s = i & 63;
        As[n * 65 + s] = A[i];
    }
    cs[tid] = Cv[tid];
    float w0 = Bv[tid];
    ws[tid] = w0;
    Wd[tid] = w0;                   // d = 0
    __syncthreads();

    for (int d = 1; d < DMAX; d++) {
        float a0 = 0.f, a1 = 0.f, a2 = 0.f, a3 = 0.f;
        #pragma unroll
        for (int s = 0; s < 64; s += 4) {
            a0 += As[tid * 65 + s + 0] * ws[s + 0];
            a1 += As[tid * 65 + s + 1] * ws[s + 1];
            a2 += As[tid * 65 + s + 2] * ws[s + 2];
            a3 += As[tid * 65 + s + 3] * ws[s + 3];
        }
        float wn = (a0 + a1) + (a2 + a3);
        __syncthreads();
        ws[tid] = wn;
        Wd[d * 65 + tid] = wn;
        __syncthreads();
    }
    // g[d] = C . Wd[d]
    float acc = 0.f;
    #pragma unroll
    for (int j = 0; j < 64; j++) acc += cs[j] * Wd[tid * 65 + j];
    g_g[tid] = acc;
}

// ---------------- pass 2b: u via popc, then y = D*u + g (*) u --------------------
__global__ void y_kernel(const float* __restrict__ Dp)
{
    __shared__ float u_s[TC + DMAX];   // u_s[i] = u[t0 + i - (DMAX-1)]
    __shared__ float g_s[DMAX];

    const int b     = blockIdx.x >> 3;      // SEQ/TC = 8 chunks per batch
    const int chunk = blockIdx.x & 7;
    const int t0    = chunk * TC;
    const int tid   = threadIdx.x;          // 256

    if (tid < DMAX) g_s[tid] = g_g[tid];

    for (int i = tid; i < TC + DMAX - 1; i += 256) {
        int t = t0 + i - (DMAX - 1);
        float uv = 0.0f;
        if (t >= 0) {
            int cnt = 0;
            #pragma unroll
            for (int w = 0; w < NWRD; w++) cnt += __popc(g_spikebits[b][w][t]);
            uv = (float)cnt * (1.0f / (float)HID);
        }
        u_s[i] = uv;
    }
    __syncthreads();

    const float Ds = *Dp;
    for (int i = tid; i < TC; i += 256) {
        float acc = Ds * u_s[i + DMAX - 1];
        #pragma unroll
        for (int d = 0; d < DMAX; d++)
            acc += g_s[d] * u_s[i + DMAX - 1 - d];
        g_y[b][t0 + i] = acc;
    }
}

// ---------------- pass 3: out[b][t][h] = spike_bit + y[b][t] ---------------------
__global__ void __launch_bounds__(256) out_kernel(float4* __restrict__ out)
{
    const int idx = blockIdx.x * 256 + threadIdx.x;   // one float4 (4 hidden) each
    const int h4  = idx & (HID / 4 - 1);              // 0..255
    const int bt  = idx >> 8;
    const int t   = bt & (SEQ - 1);
    const int b   = bt >> 12;

    const unsigned bits = g_spikebits[b][h4 >> 3][t]; // word for h0 = h4*4
    const float y = g_y[b][t];
    const int sh = (h4 & 7) * 4;

    float4 o;
    o.x = (float)((bits >> (sh + 0)) & 1u) + y;
    o.y = (float)((bits >> (sh + 1)) & 1u) + y;
    o.z = (float)((bits >> (sh + 2)) & 1u) + y;
    o.w = (float)((bits >> (sh + 3)) & 1u) + y;
    out[idx] = o;
}

// ---------------- launch ----------------------------------------------------------
extern "C" void kernel_launch(void* const* d_in, const int* in_sizes, int n_in,
                              void* d_out, int out_size)
{
    const float* x  = (const float*)d_in[0];   // (8, 4096, 1024) f32
    const float* A  = (const float*)d_in[1];   // (64, 64)
    const float* Bv = (const float*)d_in[2];   // (64, 1)
    const float* Cv = (const float*)d_in[3];   // (1, 64)
    const float* Dp = (const float*)d_in[4];   // (1, 1)

    snn_kernel<<<128, 64>>>(x);
    g_kernel<<<1, 64>>>(A, Bv, Cv);
    y_kernel<<<B_SZ * (SEQ / TC), 256>>>(Dp);
    out_kernel<<<(B_SZ * SEQ * HID / 4) / 256, 256>>>((float4*)d_out);
}